// round 1
// baseline (speedup 1.0000x reference)
#include <cuda_runtime.h>

// Problem constants
#define B_      32
#define L_      32768
#define M_      32
#define D_      128
#define K_      16
#define STRIDE_ 8
#define P_      4095        // (L - K)/STRIDE + 1
#define TP      128         // patches per CTA tile
#define CG      512         // GEMM K dim = M*K
#define CC      64          // K-chunk (2 k-values x 32 m)
#define NCHUNK  8

// Pre-transposed weights: wT[c][d], c = k*32 + m  (256 KB device scratch, allowed)
__device__ float g_wT[CG * D_];

__global__ void transpose_w_kernel(const float* __restrict__ w) {
    int idx = blockIdx.x * blockDim.x + threadIdx.x;
    if (idx >= CG * D_) return;
    int c = idx >> 7;       // c index
    int d = idx & 127;
    int k = c >> 5;
    int m = c & 31;
    g_wT[idx] = w[d * CG + m * K_ + k];
}

typedef unsigned long long ull;

__device__ __forceinline__ void ffma2(ull& a, ull x, ull w) {
    asm("fma.rn.f32x2 %0, %1, %2, %0;" : "+l"(a) : "l"(x), "l"(w));
}
__device__ __forceinline__ float2 unpack2(ull v) {
    float2 r;
    asm("mov.b64 {%0, %1}, %2;" : "=f"(r.x), "=f"(r.y) : "l"(v));
    return r;
}

// smem layout (floats):
//   as  [64][130]           8320 floats  (x tile, [cc][p], stride 130: 8B-aligned, 2-way STS conflict only)
//   ws2 [64][128] float2   16384 floats  (w duplicated {w,w} pairs)
//   smed[128]                128 floats
//   cb  [128]                128 floats
#define AS_STRIDE 130
#define WS2_OFF   8320
#define SMED_OFF  (WS2_OFF + 16384)
#define CB_OFF    (SMED_OFF + 128)
#define SMEM_FLOATS (CB_OFF + 128)

__global__ __launch_bounds__(256, 2)
void patch_encoder_kernel(const float* __restrict__ x,
                          const float* __restrict__ ts,
                          const float* __restrict__ bias,
                          float* __restrict__ out) {
    extern __shared__ float sm[];
    float*  as_  = sm;
    float2* ws2  = (float2*)(sm + WS2_OFF);
    float*  smed = sm + SMED_OFF;
    float*  cb   = sm + CB_OFF;

    const int tid  = threadIdx.x;
    const int tx   = tid & 15;      // d-group
    const int ty   = tid >> 4;      // p-group
    const int lane = tid & 31;
    const int wid  = tid >> 5;
    const int p0   = blockIdx.x * TP;
    const int b    = blockIdx.y;

    // ---- prepass: bias + window medians (16-elem odd-even transposition sort) ----
    if (tid < D_) cb[tid] = bias[tid];
    if (tid < TP) {
        int p = p0 + tid;
        float med = 0.f;
        if (p < P_) {
            float v[K_];
            const float* tp = ts + b * L_ + p * STRIDE_;
            #pragma unroll
            for (int i = 0; i < K_; i++) v[i] = tp[i];
            #pragma unroll
            for (int pass = 0; pass < K_; pass++) {
                if ((pass & 1) == 0) {
                    #pragma unroll
                    for (int i = 0; i < K_ - 1; i += 2) {
                        float lo = fminf(v[i], v[i + 1]);
                        float hi = fmaxf(v[i], v[i + 1]);
                        v[i] = lo; v[i + 1] = hi;
                    }
                } else {
                    #pragma unroll
                    for (int i = 1; i < K_ - 1; i += 2) {
                        float lo = fminf(v[i], v[i + 1]);
                        float hi = fmaxf(v[i], v[i + 1]);
                        v[i] = lo; v[i + 1] = hi;
                    }
                }
            }
            med = v[(K_ - 1) / 2];
        }
        smed[tid] = med;
    }

    // ---- main GEMM: acc[pp][dd] f32x2 packed along p ----
    ull acc[4][8];
    #pragma unroll
    for (int i = 0; i < 4; i++)
        #pragma unroll
        for (int j = 0; j < 8; j++) acc[i][j] = 0ull;

    const float* xb = x + (size_t)b * L_ * M_;

    for (int ci = 0; ci < NCHUNK; ci++) {
        __syncthreads();
        // stage x chunk: rows (8p + 2ci + kk), full 32-float coalesced rows, one warp per row
        #pragma unroll 4
        for (int idx = wid; idx < 2 * TP; idx += 8) {
            int pl = idx >> 1;
            int kk = idx & 1;
            int p  = p0 + pl;
            float v = 0.f;
            if (p < P_) {
                int grow = p * STRIDE_ + 2 * ci + kk;
                v = xb[grow * M_ + lane];
            }
            as_[(kk * 32 + lane) * AS_STRIDE + pl] = v;
        }
        // stage w chunk as duplicated {w,w} pairs
        #pragma unroll 4
        for (int i = tid; i < CC * D_; i += 256) {
            float v = g_wT[ci * CC * D_ + i];
            ws2[i] = make_float2(v, v);
        }
        __syncthreads();

        const ull*        asw = (const ull*)as_;           // row stride = 65 ull
        const ulonglong2* wsp = (const ulonglong2*)ws2;    // row stride = 64 ull2

        #pragma unroll 2
        for (int cc = 0; cc < CC; cc++) {
            ull xp[4];
            xp[0] = asw[cc * 65 + 2 * ty];           // p: 4ty,   4ty+1
            xp[1] = asw[cc * 65 + 2 * ty + 1];       // p: 4ty+2, 4ty+3
            xp[2] = asw[cc * 65 + 32 + 2 * ty];      // p: 64+4ty, +1
            xp[3] = asw[cc * 65 + 32 + 2 * ty + 1];  // p: 64+4ty+2, +3
            ulonglong2 w0 = wsp[cc * 64 + tx];       // d: 2tx,    2tx+1
            ulonglong2 w1 = wsp[cc * 64 + 16 + tx];  // d: 32+2tx, 32+2tx+1
            ulonglong2 w2 = wsp[cc * 64 + 32 + tx];  // d: 64+2tx, ...
            ulonglong2 w3 = wsp[cc * 64 + 48 + tx];  // d: 96+2tx, ...
            #pragma unroll
            for (int pp = 0; pp < 4; pp++) {
                ffma2(acc[pp][0], xp[pp], w0.x);
                ffma2(acc[pp][1], xp[pp], w0.y);
                ffma2(acc[pp][2], xp[pp], w1.x);
                ffma2(acc[pp][3], xp[pp], w1.y);
                ffma2(acc[pp][4], xp[pp], w2.x);
                ffma2(acc[pp][5], xp[pp], w2.y);
                ffma2(acc[pp][6], xp[pp], w3.x);
                ffma2(acc[pp][7], xp[pp], w3.y);
            }
        }
    }

    // ---- epilogue: bias + sinusoidal PE from median timestamp ----
    float dt[4];
    #pragma unroll
    for (int j = 0; j < 4; j++) {
        float fi = (float)(tx + 16 * j);
        dt[j] = __expf(fi * -0.14391156831f);  // -ln(10000)/64
    }
    float2 cbv[4];
    #pragma unroll
    for (int j = 0; j < 4; j++) {
        int d0 = 2 * tx + 32 * j;
        cbv[j] = make_float2(cb[d0], cb[d0 + 1]);
    }

    float* outb = out + (size_t)b * P_ * D_;
    #pragma unroll
    for (int r = 0; r < 8; r++) {
        int pl = 4 * ty + (r & 3) + ((r >= 4) ? 64 : 0);
        int p  = p0 + pl;
        if (p >= P_) continue;
        float med = smed[pl];
        float* orow = outb + (size_t)p * D_;
        int pp = r >> 1;
        int hi = r & 1;
        #pragma unroll
        for (int j = 0; j < 4; j++) {
            float sn, cs;
            __sincosf(med * dt[j], &sn, &cs);
            float2 a0 = unpack2(acc[pp][2 * j]);      // even d (sin slot)
            float2 a1 = unpack2(acc[pp][2 * j + 1]);  // odd d  (cos slot)
            float e = hi ? a0.y : a0.x;
            float o = hi ? a1.y : a1.x;
            float2 res = make_float2(e + cbv[j].x + sn, o + cbv[j].y + cs);
            *(float2*)(orow + 2 * tx + 32 * j) = res;
        }
    }
}

extern "C" void kernel_launch(void* const* d_in, const int* in_sizes, int n_in,
                              void* d_out, int out_size) {
    const float* x    = (const float*)d_in[0];
    const float* ts   = (const float*)d_in[1];
    const float* w    = (const float*)d_in[2];
    const float* bias = (const float*)d_in[3];
    float* out = (float*)d_out;

    transpose_w_kernel<<<(CG * D_ + 255) / 256, 256>>>(w);

    cudaFuncSetAttribute(patch_encoder_kernel,
                         cudaFuncAttributeMaxDynamicSharedMemorySize,
                         SMEM_FLOATS * (int)sizeof(float));
    dim3 grid((P_ + TP - 1) / TP, B_);
    patch_encoder_kernel<<<grid, 256, SMEM_FLOATS * sizeof(float)>>>(x, ts, bias, out);
}

// round 3
// speedup vs baseline: 2.8886x; 2.8886x over previous
#include <cuda_runtime.h>
#include <cuda_bf16.h>
#include <cstdint>

// ---------------- problem constants ----------------
#define B_      32
#define L_      32768
#define M_      32
#define KW      16
#define D_      128
#define STRIDE_ 8
#define P_      4095
#define NCH     16           // K chunks (32 fp32 each, total 512)

// ---------------- smem layout (bytes) ----------------
// per buffer: Ah 8K | Al 8K | Bh 8K | Bl 8K = 32KB, double buffered
#define TILE_B   32768
#define OFF_AH(b) ((b) * TILE_B + 0)
#define OFF_AL(b) ((b) * TILE_B + 8192)
#define OFF_BH(b) ((b) * TILE_B + 16384)
#define OFF_BL(b) ((b) * TILE_B + 24576)
#define OFF_SMED (2 * TILE_B)
#define OFF_CB   (2 * TILE_B + 512)
#define SM_TOTAL (2 * TILE_B + 1024)

// ---------------- precomputed W fragments (bf16 hi/lo split) ----------------
// layout: [chunk(16)][ks(2)][ntile(16)][lane(32)][reg(2)]  (u32 = bf16x2)
__device__ uint32_t g_Bh[NCH * 2048];
__device__ uint32_t g_Bl[NCH * 2048];

__global__ void prep_w_kernel(const float* __restrict__ w) {
    int idx = blockIdx.x * 256 + threadIdx.x;       // 0..32767
    int reg  = idx & 1;
    int lane = (idx >> 1) & 31;
    int nt   = (idx >> 6) & 15;
    int ks   = (idx >> 10) & 1;
    int ci   = idx >> 11;
    int n = nt * 8 + (lane >> 2);                   // d row
    int c = ci * 32 + ks * 16 + reg * 8 + 2 * (lane & 3);
    int m0 = c & 31, kk = c >> 5;                   // c = kk*32 + m
    float v0 = w[n * 512 + m0 * 16 + kk];
    float v1 = w[n * 512 + (m0 + 1) * 16 + kk];
    uint32_t hi;
    asm("cvt.rn.bf16x2.f32 %0, %1, %2;" : "=r"(hi) : "f"(v1), "f"(v0));
    float h0 = __uint_as_float(hi << 16);
    float h1 = __uint_as_float(hi & 0xffff0000u);
    uint32_t lo;
    asm("cvt.rn.bf16x2.f32 %0, %1, %2;" : "=r"(lo) : "f"(v1 - h1), "f"(v0 - h0));
    g_Bh[idx] = hi;
    g_Bl[idx] = lo;
}

// ---------------- mma wrapper ----------------
__device__ __forceinline__ void mma_bf16(float* c, uint4 a, uint2 b) {
    asm volatile(
        "mma.sync.aligned.m16n8k16.row.col.f32.bf16.bf16.f32 "
        "{%0,%1,%2,%3}, {%4,%5,%6,%7}, {%8,%9}, {%0,%1,%2,%3};"
        : "+f"(c[0]), "+f"(c[1]), "+f"(c[2]), "+f"(c[3])
        : "r"(a.x), "r"(a.y), "r"(a.z), "r"(a.w), "r"(b.x), "r"(b.y));
}

// ---------------- main kernel ----------------
__global__ __launch_bounds__(256, 2)
void encoder_hmma_kernel(const float* __restrict__ x,
                         const float* __restrict__ ts,
                         const float* __restrict__ bias,
                         float* __restrict__ out) {
    extern __shared__ char smem[];
    const int tid  = threadIdx.x;
    const int lane = tid & 31;
    const int wid  = tid >> 5;
    const int wm   = wid >> 1;     // 0..3  (p rows of 32)
    const int wn   = wid & 1;      // 0..1  (d cols of 64)
    const int p0   = blockIdx.x * 128;
    const int b    = blockIdx.y;

    float* smed = (float*)(smem + OFF_SMED);
    float* cb   = (float*)(smem + OFF_CB);

    // ---- prepass: bias + window medians ----
    if (tid < D_) cb[tid] = bias[tid];
    if (tid < 128) {
        int p = p0 + tid;
        float med = 0.f;
        if (p < P_) {
            float v[KW];
            const float* tp = ts + b * L_ + p * STRIDE_;
            #pragma unroll
            for (int i = 0; i < KW; i++) v[i] = tp[i];
            #pragma unroll
            for (int pass = 0; pass < KW; pass++) {
                int st = pass & 1;
                #pragma unroll
                for (int i = 0; i < KW - 1; i++) {
                    if ((i & 1) == st) {
                        float lo = fminf(v[i], v[i + 1]);
                        float hi = fmaxf(v[i], v[i + 1]);
                        v[i] = lo; v[i + 1] = hi;
                    }
                }
            }
            med = v[(KW - 1) / 2];
        }
        smed[tid] = med;
    }

    const float* xb = x + (size_t)b * (L_ * M_);

    float acc[2][8][4];
    #pragma unroll
    for (int i = 0; i < 2; i++)
        #pragma unroll
        for (int j = 0; j < 8; j++)
            #pragma unroll
            for (int q = 0; q < 4; q++) acc[i][j][q] = 0.f;

    // ---- staging lambdas (manually inlined) ----
    // A: x fp32 -> hi/lo bf16x2 fragments: [ks(2)][mt(8)][lane(32)][a(4)] u32
    // B: coalesced copy of precomputed fragments
    #define STAGE_A(BUF, CI) do {                                             \
        uint32_t* Ah = (uint32_t*)(smem + OFF_AH(BUF));                       \
        uint32_t* Al = (uint32_t*)(smem + OFF_AL(BUF));                       \
        _Pragma("unroll")                                                     \
        for (int i = 0; i < 8; i++) {                                         \
            int idx = tid + (i << 8);                                         \
            int row = idx >> 4;                                               \
            int j2  = idx & 15;                                               \
            int p = p0 + row;                                                 \
            float2 v = make_float2(0.f, 0.f);                                 \
            if (p < P_) v = *(const float2*)(xb + (size_t)p * 256 + (CI) * 32 + j2 * 2); \
            uint32_t hi;                                                      \
            asm("cvt.rn.bf16x2.f32 %0, %1, %2;" : "=r"(hi) : "f"(v.y), "f"(v.x)); \
            float h0 = __uint_as_float(hi << 16);                             \
            float h1 = __uint_as_float(hi & 0xffff0000u);                     \
            uint32_t lo;                                                      \
            asm("cvt.rn.bf16x2.f32 %0, %1, %2;" : "=r"(lo) : "f"(v.y - h1), "f"(v.x - h0)); \
            int mt = row >> 4, g = row & 7, rh = (row >> 3) & 1;              \
            int t = j2 & 3, ks = j2 >> 3, ch = (j2 >> 2) & 1;                 \
            int slot = (((ks << 3) + mt) * 32 + (g << 2) + t) * 4 + (ch << 1) + rh; \
            Ah[slot] = hi;                                                    \
            Al[slot] = lo;                                                    \
        }                                                                     \
    } while (0)

    #define STAGE_B(BUF, CI) do {                                             \
        uint4* dBh = (uint4*)(smem + OFF_BH(BUF));                            \
        uint4* dBl = (uint4*)(smem + OFF_BL(BUF));                            \
        const uint4* sBh = (const uint4*)(g_Bh + (CI) * 2048);                \
        const uint4* sBl = (const uint4*)(g_Bl + (CI) * 2048);                \
        _Pragma("unroll")                                                     \
        for (int i = 0; i < 2; i++) {                                         \
            int idx = tid + (i << 8);                                         \
            dBh[idx] = sBh[idx];                                              \
            dBl[idx] = sBl[idx];                                              \
        }                                                                     \
    } while (0)

    #define COMPUTE(BUF) do {                                                 \
        const uint4* Ah4 = (const uint4*)(smem + OFF_AH(BUF));                \
        const uint4* Al4 = (const uint4*)(smem + OFF_AL(BUF));                \
        const uint2* Bh2 = (const uint2*)(smem + OFF_BH(BUF));                \
        const uint2* Bl2 = (const uint2*)(smem + OFF_BL(BUF));                \
        _Pragma("unroll")                                                     \
        for (int ks = 0; ks < 2; ks++) {                                      \
            uint4 ah0 = Ah4[((ks << 3) + wm * 2 + 0) * 32 + lane];            \
            uint4 ah1 = Ah4[((ks << 3) + wm * 2 + 1) * 32 + lane];            \
            uint4 al0 = Al4[((ks << 3) + wm * 2 + 0) * 32 + lane];            \
            uint4 al1 = Al4[((ks << 3) + wm * 2 + 1) * 32 + lane];            \
            _Pragma("unroll")                                                 \
            for (int nt = 0; nt < 8; nt++) {                                  \
                uint2 bh = Bh2[((ks << 4) + wn * 8 + nt) * 32 + lane];        \
                uint2 bl = Bl2[((ks << 4) + wn * 8 + nt) * 32 + lane];        \
                mma_bf16(acc[0][nt], ah0, bh);                                \
                mma_bf16(acc[0][nt], ah0, bl);                                \
                mma_bf16(acc[0][nt], al0, bh);                                \
                mma_bf16(acc[1][nt], ah1, bh);                                \
                mma_bf16(acc[1][nt], ah1, bl);                                \
                mma_bf16(acc[1][nt], al1, bh);                                \
            }                                                                 \
        }                                                                     \
    } while (0)

    // ---- pipeline ----
    STAGE_A(0, 0);
    STAGE_B(0, 0);
    __syncthreads();

    #pragma unroll 4
    for (int ci = 0; ci < NCH; ci++) {
        int buf = ci & 1;
        if (ci + 1 < NCH) {
            STAGE_A(buf ^ 1, ci + 1);
            STAGE_B(buf ^ 1, ci + 1);
        }
        COMPUTE(buf);
        __syncthreads();
    }

    // ---- epilogue: bias + sinusoidal PE from median, write out ----
    {
        const int t = lane & 3, g = lane >> 2;
        float dt[8];
        #pragma unroll
        for (int nt = 0; nt < 8; nt++) {
            int i = wn * 32 + nt * 4 + t;               // d0/2
            dt[nt] = __expf((float)i * -0.14391156831f); // -ln(10000)*2/128
        }
        #pragma unroll
        for (int mt = 0; mt < 2; mt++) {
            int pl = wm * 32 + mt * 16 + g;
            #pragma unroll
            for (int half = 0; half < 2; half++) {
                int prow = pl + half * 8;
                int p = p0 + prow;
                if (p >= P_) continue;
                float med = smed[prow];
                float* orow = out + ((size_t)b * P_ + p) * D_;
                #pragma unroll
                for (int nt = 0; nt < 8; nt++) {
                    int d0 = wn * 64 + nt * 8 + 2 * t;
                    float sn, cs;
                    __sincosf(med * dt[nt], &sn, &cs);
                    float2 o;
                    o.x = acc[mt][nt][half * 2 + 0] + cb[d0] + sn;
                    o.y = acc[mt][nt][half * 2 + 1] + cb[d0 + 1] + cs;
                    *(float2*)(orow + d0) = o;
                }
            }
        }
    }
}

extern "C" void kernel_launch(void* const* d_in, const int* in_sizes, int n_in,
                              void* d_out, int out_size) {
    const float* x    = (const float*)d_in[0];
    const float* ts   = (const float*)d_in[1];
    const float* w    = (const float*)d_in[2];
    const float* bias = (const float*)d_in[3];
    float* out = (float*)d_out;

    prep_w_kernel<<<128, 256>>>(w);

    cudaFuncSetAttribute(encoder_hmma_kernel,
                         cudaFuncAttributeMaxDynamicSharedMemorySize, SM_TOTAL);
    dim3 grid(32, B_);
    encoder_hmma_kernel<<<grid, 256, SM_TOTAL>>>(x, ts, bias, out);
}

// round 5
// speedup vs baseline: 4.3260x; 1.4976x over previous
#include <cuda_runtime.h>
#include <cuda_fp16.h>
#include <cstdint>

// ---------------- problem constants ----------------
#define B_      32
#define L_      32768
#define M_      32
#define KW      16
#define D_      128
#define STRIDE_ 8
#define P_      4095
#define NCH     16           // K chunks (32 fp32 each, total 512)

// ---------------- smem layout (bytes) ----------------
// per buffer: Ah 8K | Al 8K | Bh 8K = 24KB, double buffered
#define TILE_B   24576
#define OFF_AH(b) ((b) * TILE_B + 0)
#define OFF_AL(b) ((b) * TILE_B + 8192)
#define OFF_BH(b) ((b) * TILE_B + 16384)
#define OFF_SMED (2 * TILE_B)
#define OFF_CB   (2 * TILE_B + 512)
#define SM_TOTAL (2 * TILE_B + 1024)

// ---------------- precomputed W fragments (fp16) ----------------
// layout: [chunk(16)][ks(2)][ntpair(8)][lane(32)][4 u32]  (u32 = fp16x2)
// 4 u32 per slot = {nt0.b0, nt0.b1, nt1.b0, nt1.b1}, nt = 2*ntp + (r>>1)
__device__ uint32_t g_Bh[NCH * 2048];

__global__ void prep_w_kernel(const float* __restrict__ w) {
    int idx = blockIdx.x * 256 + threadIdx.x;       // 0..32767
    int r    = idx & 3;
    int lane = (idx >> 2) & 31;
    int ntp  = (idx >> 7) & 7;
    int ks   = (idx >> 10) & 1;
    int ci   = idx >> 11;
    int nt   = ntp * 2 + (r >> 1);
    int breg = r & 1;
    int n = nt * 8 + (lane >> 2);                   // d row
    int c = ci * 32 + ks * 16 + breg * 8 + 2 * (lane & 3);
    int m0 = c & 31, kk = c >> 5;                   // c = kk*32 + m
    float v0 = w[n * 512 + m0 * 16 + kk];
    float v1 = w[n * 512 + (m0 + 1) * 16 + kk];
    __half2 h = __floats2half2_rn(v0, v1);
    g_Bh[idx] = *(uint32_t*)&h;
}

// ---------------- mma wrapper (fp16) ----------------
__device__ __forceinline__ void mma_f16(float* c, uint4 a, uint32_t b0, uint32_t b1) {
    asm volatile(
        "mma.sync.aligned.m16n8k16.row.col.f32.f16.f16.f32 "
        "{%0,%1,%2,%3}, {%4,%5,%6,%7}, {%8,%9}, {%0,%1,%2,%3};"
        : "+f"(c[0]), "+f"(c[1]), "+f"(c[2]), "+f"(c[3])
        : "r"(a.x), "r"(a.y), "r"(a.z), "r"(a.w), "r"(b0), "r"(b1));
}

__device__ __forceinline__ uint32_t smem_u32(const void* p) {
    uint32_t a;
    asm("{ .reg .u64 t; cvta.to.shared.u64 t, %1; cvt.u32.u64 %0, t; }" : "=r"(a) : "l"(p));
    return a;
}

// ---------------- main kernel ----------------
__global__ __launch_bounds__(256, 2)
void encoder_hmma_kernel(const float* __restrict__ x,
                         const float* __restrict__ ts,
                         const float* __restrict__ bias,
                         float* __restrict__ out) {
    extern __shared__ char smem[];
    const int tid  = threadIdx.x;
    const int lane = tid & 31;
    const int wid  = tid >> 5;
    const int wm   = wid >> 1;     // 0..3  (p rows of 32)
    const int wn   = wid & 1;      // 0..1  (d cols of 64)
    const int p0   = blockIdx.x * 128;
    const int b    = blockIdx.y;

    float* smed = (float*)(smem + OFF_SMED);
    float* cb   = (float*)(smem + OFF_CB);

    const float* xb = x + (size_t)b * (L_ * M_);

    float acc[2][8][4];
    #pragma unroll
    for (int i = 0; i < 2; i++)
        #pragma unroll
        for (int j = 0; j < 8; j++)
            #pragma unroll
            for (int q = 0; q < 4; q++) acc[i][j][q] = 0.f;

    // x prefetch registers: 8 float2 per chunk (row = idx>>4, j2 = idx&15)
    float2 xr[8];

    #define LOAD_X(CI) do {                                                   \
        _Pragma("unroll")                                                     \
        for (int i = 0; i < 8; i++) {                                         \
            int idx = tid + (i << 8);                                         \
            int row = idx >> 4;                                               \
            int j2  = idx & 15;                                               \
            int p = p0 + row;                                                 \
            xr[i] = make_float2(0.f, 0.f);                                    \
            if (p < P_) xr[i] = *(const float2*)(xb + (size_t)p * 256 + (CI) * 32 + j2 * 2); \
        }                                                                     \
    } while (0)

    #define STS_A(BUF) do {                                                   \
        uint32_t* Ah = (uint32_t*)(smem + OFF_AH(BUF));                       \
        uint32_t* Al = (uint32_t*)(smem + OFF_AL(BUF));                       \
        _Pragma("unroll")                                                     \
        for (int i = 0; i < 8; i++) {                                         \
            int idx = tid + (i << 8);                                         \
            int row = idx >> 4;                                               \
            int j2  = idx & 15;                                               \
            __half h0 = __float2half_rn(xr[i].x);                             \
            __half h1 = __float2half_rn(xr[i].y);                             \
            __half l0 = __float2half_rn(xr[i].x - __half2float(h0));          \
            __half l1 = __float2half_rn(xr[i].y - __half2float(h1));          \
            __half2 hv = __halves2half2(h0, h1);                              \
            __half2 lv = __halves2half2(l0, l1);                              \
            int mt = row >> 4, g = row & 7, rh = (row >> 3) & 1;              \
            int t = j2 & 3, ks = j2 >> 3, ch = (j2 >> 2) & 1;                 \
            int slot = (((ks << 3) + mt) * 32 + (g << 2) + t) * 4 + (ch << 1) + rh; \
            Ah[slot] = *(uint32_t*)&hv;                                       \
            Al[slot] = *(uint32_t*)&lv;                                       \
        }                                                                     \
    } while (0)

    #define CPASYNC_B(BUF, CI) do {                                           \
        uint32_t dst = smem_u32(smem + OFF_BH(BUF)) + tid * 16;               \
        const uint4* src = (const uint4*)(g_Bh + (CI) * 2048) + tid;          \
        asm volatile("cp.async.ca.shared.global [%0], [%1], 16;"              \
                     :: "r"(dst), "l"(src));                                  \
        asm volatile("cp.async.ca.shared.global [%0], [%1], 16;"              \
                     :: "r"(dst + 4096), "l"(src + 256));                     \
        asm volatile("cp.async.commit_group;");                               \
    } while (0)

    #define CPASYNC_WAIT() asm volatile("cp.async.wait_group 0;" ::: "memory")

    #define COMPUTE(BUF) do {                                                 \
        const uint4* Ah4 = (const uint4*)(smem + OFF_AH(BUF));                \
        const uint4* Al4 = (const uint4*)(smem + OFF_AL(BUF));                \
        const uint4* Bh4 = (const uint4*)(smem + OFF_BH(BUF));                \
        _Pragma("unroll")                                                     \
        for (int ks = 0; ks < 2; ks++) {                                      \
            uint4 ah0 = Ah4[((ks << 3) + wm * 2 + 0) * 32 + lane];            \
            uint4 ah1 = Ah4[((ks << 3) + wm * 2 + 1) * 32 + lane];            \
            uint4 al0 = Al4[((ks << 3) + wm * 2 + 0) * 32 + lane];            \
            uint4 al1 = Al4[((ks << 3) + wm * 2 + 1) * 32 + lane];            \
            _Pragma("unroll")                                                 \
            for (int ntp = 0; ntp < 4; ntp++) {                               \
                uint4 bb = Bh4[((ks << 3) + wn * 4 + ntp) * 32 + lane];       \
                mma_f16(acc[0][2 * ntp],     ah0, bb.x, bb.y);                \
                mma_f16(acc[0][2 * ntp],     al0, bb.x, bb.y);                \
                mma_f16(acc[1][2 * ntp],     ah1, bb.x, bb.y);                \
                mma_f16(acc[1][2 * ntp],     al1, bb.x, bb.y);                \
                mma_f16(acc[0][2 * ntp + 1], ah0, bb.z, bb.w);                \
                mma_f16(acc[0][2 * ntp + 1], al0, bb.z, bb.w);                \
                mma_f16(acc[1][2 * ntp + 1], ah1, bb.z, bb.w);                \
                mma_f16(acc[1][2 * ntp + 1], al1, bb.z, bb.w);                \
            }                                                                 \
        }                                                                     \
    } while (0)

    // ---- prologue: start chunk-0 staging, then medians/bias ----
    CPASYNC_B(0, 0);
    LOAD_X(0);

    if (tid < D_) cb[tid] = bias[tid];
    if (tid < 128) {
        int p = p0 + tid;
        float med = 0.f;
        if (p < P_) {
            float v[KW];
            const float* tp = ts + b * L_ + p * STRIDE_;
            #pragma unroll
            for (int i = 0; i < KW; i++) v[i] = tp[i];
            #pragma unroll
            for (int pass = 0; pass < KW; pass++) {
                int st = pass & 1;
                #pragma unroll
                for (int i = 0; i < KW - 1; i++) {
                    if ((i & 1) == st) {
                        float lo = fminf(v[i], v[i + 1]);
                        float hi = fmaxf(v[i], v[i + 1]);
                        v[i] = lo; v[i + 1] = hi;
                    }
                }
            }
            med = v[(KW - 1) / 2];
        }
        smed[tid] = med;
    }

    STS_A(0);
    CPASYNC_WAIT();
    __syncthreads();

    // ---- pipelined main loop ----
    for (int ci = 0; ci < NCH; ci++) {
        int buf = ci & 1;
        if (ci + 1 < NCH) {
            CPASYNC_B(buf ^ 1, ci + 1);
            LOAD_X(ci + 1);
        }
        COMPUTE(buf);
        if (ci + 1 < NCH) {
            STS_A(buf ^ 1);
            CPASYNC_WAIT();
        }
        __syncthreads();
    }

    // ---- epilogue: bias + sinusoidal PE from median, write out ----
    {
        const int t = lane & 3, g = lane >> 2;
        float dt[8];
        #pragma unroll
        for (int nt = 0; nt < 8; nt++) {
            int i = wn * 32 + nt * 4 + t;                // d0/2
            dt[nt] = __expf((float)i * -0.14391156831f); // -ln(10000)*2/128
        }
        #pragma unroll
        for (int mt = 0; mt < 2; mt++) {
            int pl = wm * 32 + mt * 16 + g;
            #pragma unroll
            for (int half = 0; half < 2; half++) {
                int prow = pl + half * 8;
                int p = p0 + prow;
                if (p >= P_) continue;
                float med = smed[prow];
                float* orow = out + ((size_t)b * P_ + p) * D_;
                #pragma unroll
                for (int nt = 0; nt < 8; nt++) {
                    int d0 = wn * 64 + nt * 8 + 2 * t;
                    float sn, cs;
                    __sincosf(med * dt[nt], &sn, &cs);
                    float2 o;
                    o.x = acc[mt][nt][half * 2 + 0] + cb[d0] + sn;
                    o.y = acc[mt][nt][half * 2 + 1] + cb[d0 + 1] + cs;
                    *(float2*)(orow + d0) = o;
                }
            }
        }
    }
}

extern "C" void kernel_launch(void* const* d_in, const int* in_sizes, int n_in,
                              void* d_out, int out_size) {
    const float* x    = (const float*)d_in[0];
    const float* ts   = (const float*)d_in[1];
    const float* w    = (const float*)d_in[2];
    const float* bias = (const float*)d_in[3];
    float* out = (float*)d_out;

    prep_w_kernel<<<128, 256>>>(w);

    cudaFuncSetAttribute(encoder_hmma_kernel,
                         cudaFuncAttributeMaxDynamicSharedMemorySize, SM_TOTAL);
    dim3 grid(32, B_);
    encoder_hmma_kernel<<<grid, 256, SM_TOTAL>>>(x, ts, bias, out);
}

// round 6
// speedup vs baseline: 4.8888x; 1.1301x over previous
#include <cuda_runtime.h>
#include <cuda_fp16.h>
#include <cstdint>

// ---------------- problem constants ----------------
#define B_      32
#define L_      32768
#define KW      16
#define D_      128
#define STRIDE_ 8
#define P_      4095
#define NCH     16           // K chunks (32 fp32 each, total 512)

// ---------------- smem layout (bytes) ----------------
// 3-stage ring: A bufs 3x8KB @0, B bufs 3x8KB @24KB, smed @48KB, cb @48.5KB
#define OFF_A(i) ((i) * 8192)
#define OFF_B(i) (24576 + (i) * 8192)
#define OFF_SMED 49152
#define OFF_CB   49664
#define SM_TOTAL 50176

// ---------------- precomputed W fragments (fp16) ----------------
// layout: [chunk(16)][ks(2)][ntpair(8)][lane(32)][4 u32]  (u32 = fp16x2)
__device__ uint32_t g_Bh[NCH * 2048];

__global__ void prep_w_kernel(const float* __restrict__ w) {
    int idx = blockIdx.x * 256 + threadIdx.x;       // 0..32767
    int r    = idx & 3;
    int lane = (idx >> 2) & 31;
    int ntp  = (idx >> 7) & 7;
    int ks   = (idx >> 10) & 1;
    int ci   = idx >> 11;
    int nt   = ntp * 2 + (r >> 1);
    int breg = r & 1;
    int n = nt * 8 + (lane >> 2);                   // d row
    int c = ci * 32 + ks * 16 + breg * 8 + 2 * (lane & 3);
    int m0 = c & 31, kk = c >> 5;                   // c = kk*32 + m
    float v0 = w[n * 512 + m0 * 16 + kk];
    float v1 = w[n * 512 + (m0 + 1) * 16 + kk];
    __half2 h = __floats2half2_rn(v0, v1);
    g_Bh[idx] = *(uint32_t*)&h;
}

// ---------------- mma wrapper (fp16) ----------------
__device__ __forceinline__ void mma_f16(float* c, uint4 a, uint32_t b0, uint32_t b1) {
    asm volatile(
        "mma.sync.aligned.m16n8k16.row.col.f32.f16.f16.f32 "
        "{%0,%1,%2,%3}, {%4,%5,%6,%7}, {%8,%9}, {%0,%1,%2,%3};"
        : "+f"(c[0]), "+f"(c[1]), "+f"(c[2]), "+f"(c[3])
        : "r"(a.x), "r"(a.y), "r"(a.z), "r"(a.w), "r"(b0), "r"(b1));
}

__device__ __forceinline__ uint32_t smem_u32(const void* p) {
    uint32_t a;
    asm("{ .reg .u64 t; cvta.to.shared.u64 t, %1; cvt.u32.u64 %0, t; }" : "=r"(a) : "l"(p));
    return a;
}

// ---------------- main kernel ----------------
__global__ __launch_bounds__(256, 2)
void encoder_hmma_kernel(const float* __restrict__ x,
                         const float* __restrict__ ts,
                         const float* __restrict__ bias,
                         float* __restrict__ out) {
    extern __shared__ char smem[];
    const int tid  = threadIdx.x;
    const int lane = tid & 31;
    const int wid  = tid >> 5;
    const int wm   = wid >> 1;     // 0..3  (p rows of 32)
    const int wn   = wid & 1;      // 0..1  (d cols of 64)
    const int p0   = blockIdx.x * 128;
    const int b    = blockIdx.y;

    float* smed = (float*)(smem + OFF_SMED);
    float* cb   = (float*)(smem + OFF_CB);

    const float* xb = x + (size_t)b * (L_ * 32);

    float acc[2][8][4];
    #pragma unroll
    for (int i = 0; i < 2; i++)
        #pragma unroll
        for (int j = 0; j < 8; j++)
            #pragma unroll
            for (int q = 0; q < 4; q++) acc[i][j][q] = 0.f;

    float2 xrA[8], xrB[8];   // x prefetch sets (even chunks -> xrA, odd -> xrB)

    #define LOAD_X(XR, CI) do {                                               \
        _Pragma("unroll")                                                     \
        for (int i = 0; i < 8; i++) {                                         \
            int idx = tid + (i << 8);                                         \
            int row = idx >> 4;                                               \
            int j2  = idx & 15;                                               \
            int p = p0 + row;                                                 \
            XR[i] = make_float2(0.f, 0.f);                                    \
            if (p < P_) XR[i] = *(const float2*)(xb + (size_t)p * 256 + (CI) * 32 + j2 * 2); \
        }                                                                     \
    } while (0)

    #define STS_A(BUF, XR) do {                                               \
        uint32_t* Ah = (uint32_t*)(smem + OFF_A(BUF));                        \
        _Pragma("unroll")                                                     \
        for (int i = 0; i < 8; i++) {                                         \
            int idx = tid + (i << 8);                                         \
            int row = idx >> 4;                                               \
            int j2  = idx & 15;                                               \
            __half2 hv = __floats2half2_rn(XR[i].x, XR[i].y);                 \
            int mt = row >> 4, g = row & 7, rh = (row >> 3) & 1;              \
            int t = j2 & 3, ks = j2 >> 3, ch = (j2 >> 2) & 1;                 \
            int slot = (((ks << 3) + mt) * 32 + (g << 2) + t) * 4 + (ch << 1) + rh; \
            Ah[slot] = *(uint32_t*)&hv;                                       \
        }                                                                     \
    } while (0)

    #define CPASYNC_B(BUF, CI) do {                                           \
        uint32_t dst = smem_u32(smem + OFF_B(BUF)) + tid * 16;                \
        const uint4* src = (const uint4*)(g_Bh + (CI) * 2048) + tid;          \
        asm volatile("cp.async.ca.shared.global [%0], [%1], 16;"              \
                     :: "r"(dst), "l"(src));                                  \
        asm volatile("cp.async.ca.shared.global [%0], [%1], 16;"              \
                     :: "r"(dst + 4096), "l"(src + 256));                     \
    } while (0)

    #define COMMIT  asm volatile("cp.async.commit_group;")
    #define WAITG2  asm volatile("cp.async.wait_group 2;" ::: "memory")

    #define COMPUTE(BUF) do {                                                 \
        const uint4* Ah4 = (const uint4*)(smem + OFF_A(BUF));                 \
        const uint4* Bh4 = (const uint4*)(smem + OFF_B(BUF));                 \
        _Pragma("unroll")                                                     \
        for (int ks = 0; ks < 2; ks++) {                                      \
            uint4 ah0 = Ah4[((ks << 3) + wm * 2 + 0) * 32 + lane];            \
            uint4 ah1 = Ah4[((ks << 3) + wm * 2 + 1) * 32 + lane];            \
            _Pragma("unroll")                                                 \
            for (int ntp = 0; ntp < 4; ntp++) {                               \
                uint4 bb = Bh4[((ks << 3) + wn * 4 + ntp) * 32 + lane];       \
                mma_f16(acc[0][2 * ntp],     ah0, bb.x, bb.y);                \
                mma_f16(acc[1][2 * ntp],     ah1, bb.x, bb.y);                \
                mma_f16(acc[0][2 * ntp + 1], ah0, bb.z, bb.w);                \
                mma_f16(acc[1][2 * ntp + 1], ah1, bb.z, bb.w);                \
            }                                                                 \
        }                                                                     \
    } while (0)

    // ---- prologue: fill 3-stage ring (chunks 0,1 staged; chunk 2 in flight) ----
    LOAD_X(xrA, 0);
    CPASYNC_B(0, 0); COMMIT;
    CPASYNC_B(1, 1); COMMIT;
    STS_A(0, xrA);
    LOAD_X(xrB, 1);
    STS_A(1, xrB);
    LOAD_X(xrA, 2);          // chunk 2 LDG in flight; STS'd at iter 0

    if (tid < D_) cb[tid] = bias[tid];
    if (tid < 128) {
        int p = p0 + tid;
        float med = 0.f;
        if (p < P_) {
            float v[KW];
            const float* tp = ts + b * L_ + p * STRIDE_;
            #pragma unroll
            for (int i = 0; i < KW; i++) v[i] = tp[i];
            #pragma unroll
            for (int pass = 0; pass < KW; pass++) {
                int st = pass & 1;
                #pragma unroll
                for (int i = 0; i < KW - 1; i++) {
                    if ((i & 1) == st) {
                        float lo = fminf(v[i], v[i + 1]);
                        float hi = fmaxf(v[i], v[i + 1]);
                        v[i] = lo; v[i + 1] = hi;
                    }
                }
            }
            med = v[(KW - 1) / 2];
        }
        smed[tid] = med;
    }
    __syncthreads();

    // ---- pipelined main loop (unroll x2 for register-set alternation) ----
    int cbuf = 0;
    for (int ci = 0; ci < NCH; ci += 2) {
        int sbuf = (cbuf >= 1) ? cbuf - 1 : cbuf + 2;        // (cbuf+2)%3
        // even sub-iter: compute chunk ci
        if (ci + 3 < NCH) LOAD_X(xrB, ci + 3);
        if (ci + 2 < NCH) { STS_A(sbuf, xrA); CPASYNC_B(sbuf, ci + 2); }
        COMMIT;
        WAITG2;
        COMPUTE(cbuf);
        __syncthreads();
        cbuf = (cbuf >= 2) ? 0 : cbuf + 1;
        sbuf = (cbuf >= 1) ? cbuf - 1 : cbuf + 2;
        // odd sub-iter: compute chunk ci+1
        if (ci + 4 < NCH) LOAD_X(xrA, ci + 4);
        if (ci + 3 < NCH) { STS_A(sbuf, xrB); CPASYNC_B(sbuf, ci + 3); }
        COMMIT;
        WAITG2;
        COMPUTE(cbuf);
        __syncthreads();
        cbuf = (cbuf >= 2) ? 0 : cbuf + 1;
    }

    // ---- epilogue: bias + sinusoidal PE from median, write out ----
    {
        const int t = lane & 3, g = lane >> 2;
        float dt[8];
        #pragma unroll
        for (int nt = 0; nt < 8; nt++) {
            int i = wn * 32 + nt * 4 + t;                // d0/2
            dt[nt] = __expf((float)i * -0.14391156831f); // -ln(10000)*2/128
        }
        #pragma unroll
        for (int mt = 0; mt < 2; mt++) {
            int pl = wm * 32 + mt * 16 + g;
            #pragma unroll
            for (int half = 0; half < 2; half++) {
                int prow = pl + half * 8;
                int p = p0 + prow;
                if (p >= P_) continue;
                float med = smed[prow];
                float* orow = out + ((size_t)b * P_ + p) * D_;
                #pragma unroll
                for (int nt = 0; nt < 8; nt++) {
                    int d0 = wn * 64 + nt * 8 + 2 * t;
                    float sn, cs;
                    __sincosf(med * dt[nt], &sn, &cs);
                    float2 o;
                    o.x = acc[mt][nt][half * 2 + 0] + cb[d0] + sn;
                    o.y = acc[mt][nt][half * 2 + 1] + cb[d0 + 1] + cs;
                    *(float2*)(orow + d0) = o;
                }
            }
        }
    }
}

extern "C" void kernel_launch(void* const* d_in, const int* in_sizes, int n_in,
                              void* d_out, int out_size) {
    const float* x    = (const float*)d_in[0];
    const float* ts   = (const float*)d_in[1];
    const float* w    = (const float*)d_in[2];
    const float* bias = (const float*)d_in[3];
    float* out = (float*)d_out;

    prep_w_kernel<<<128, 256>>>(w);

    cudaFuncSetAttribute(encoder_hmma_kernel,
                         cudaFuncAttributeMaxDynamicSharedMemorySize, SM_TOTAL);
    dim3 grid(32, B_);
    encoder_hmma_kernel<<<grid, 256, SM_TOTAL>>>(x, ts, bias, out);
}

// round 8
// speedup vs baseline: 5.0212x; 1.0271x over previous
#include <cuda_runtime.h>
#include <cuda_fp16.h>
#include <cstdint>

// ---------------- problem constants ----------------
#define B_      32
#define L_      32768
#define KW      16
#define D_      128
#define STRIDE_ 8
#define P_      4095
#define NCH     16           // K chunks (32 fp32 each, total 512)
#define NST     8            // stages (2 chunks each)

// ---------------- smem layout (bytes) ----------------
// double buffer: A[buf] 16KB (2 chunks x 8KB) @ buf*16KB, B[buf] @ 32KB + buf*16KB
#define OFF_A(buf, c2) ((buf) * 16384 + (c2) * 8192)
#define OFF_B(buf, c2) (32768 + (buf) * 16384 + (c2) * 8192)
#define OFF_SMED 65536
#define OFF_CB   66048
#define SM_TOTAL 66560

// ---------------- precomputed W fragments (fp16) ----------------
// layout: [chunk(16)][ks(2)][ntpair(8)][lane(32)][4 u32]  (u32 = fp16x2)
__device__ uint32_t g_Bh[NCH * 2048];

__global__ void prep_w_kernel(const float* __restrict__ w) {
    int idx = blockIdx.x * 256 + threadIdx.x;       // 0..32767
    int r    = idx & 3;
    int lane = (idx >> 2) & 31;
    int ntp  = (idx >> 7) & 7;
    int ks   = (idx >> 10) & 1;
    int ci   = idx >> 11;
    int nt   = ntp * 2 + (r >> 1);
    int breg = r & 1;
    int n = nt * 8 + (lane >> 2);                   // d row
    int c = ci * 32 + ks * 16 + breg * 8 + 2 * (lane & 3);
    int m0 = c & 31, kk = c >> 5;                   // c = kk*32 + m
    float v0 = w[n * 512 + m0 * 16 + kk];
    float v1 = w[n * 512 + (m0 + 1) * 16 + kk];
    __half2 h = __floats2half2_rn(v0, v1);
    g_Bh[idx] = *(uint32_t*)&h;
}

// ---------------- mma wrapper (fp16) ----------------
__device__ __forceinline__ void mma_f16(float* c, uint4 a, uint32_t b0, uint32_t b1) {
    asm volatile(
        "mma.sync.aligned.m16n8k16.row.col.f32.f16.f16.f32 "
        "{%0,%1,%2,%3}, {%4,%5,%6,%7}, {%8,%9}, {%0,%1,%2,%3};"
        : "+f"(c[0]), "+f"(c[1]), "+f"(c[2]), "+f"(c[3])
        : "r"(a.x), "r"(a.y), "r"(a.z), "r"(a.w), "r"(b0), "r"(b1));
}

__device__ __forceinline__ uint32_t smem_u32(const void* p) {
    uint32_t a;
    asm("{ .reg .u64 t; cvta.to.shared.u64 t, %1; cvt.u32.u64 %0, t; }" : "=r"(a) : "l"(p));
    return a;
}

// ---------------- main kernel ----------------
__global__ __launch_bounds__(256, 2)
void encoder_hmma_kernel(const float* __restrict__ x,
                         const float* __restrict__ ts,
                         const float* __restrict__ bias,
                         float* __restrict__ out) {
    extern __shared__ char smem[];
    const int tid  = threadIdx.x;
    const int lane = tid & 31;
    const int wid  = tid >> 5;
    const int wm   = wid >> 1;     // 0..3  (p rows of 32)
    const int wn   = wid & 1;      // 0..1  (d cols of 64)
    const int p0   = blockIdx.x * 128;
    const int b    = blockIdx.y;

    float* smed = (float*)(smem + OFF_SMED);
    float* cb   = (float*)(smem + OFF_CB);

    const float* xb = x + (size_t)b * (L_ * 32);

    float acc[2][8][4];
    #pragma unroll
    for (int i = 0; i < 2; i++)
        #pragma unroll
        for (int j = 0; j < 8; j++)
            #pragma unroll
            for (int q = 0; q < 4; q++) acc[i][j][q] = 0.f;

    float2 xr[16];   // x prefetch for one stage (2 chunks x 8 float2)

    // load both chunks (2s, 2s+1) of stage S into xr
    #define LOAD_X(S) do {                                                    \
        _Pragma("unroll")                                                     \
        for (int i = 0; i < 16; i++) {                                        \
            int c2  = i >> 3;                                                 \
            int idx = tid + ((i & 7) << 8);                                   \
            int row = idx >> 4;                                               \
            int j2  = idx & 15;                                               \
            int p = p0 + row;                                                 \
            xr[i] = make_float2(0.f, 0.f);                                    \
            if (p < P_) xr[i] = *(const float2*)(xb + (size_t)p * 256 + ((S) * 2 + c2) * 32 + j2 * 2); \
        }                                                                     \
    } while (0)

    #define STS_A(BUF) do {                                                   \
        _Pragma("unroll")                                                     \
        for (int i = 0; i < 16; i++) {                                        \
            int c2  = i >> 3;                                                 \
            uint32_t* Ah = (uint32_t*)(smem + OFF_A(BUF, c2));                \
            int idx = tid + ((i & 7) << 8);                                   \
            int row = idx >> 4;                                               \
            int j2  = idx & 15;                                               \
            __half2 hv = __floats2half2_rn(xr[i].x, xr[i].y);                 \
            int mt = row >> 4, g = row & 7, rh = (row >> 3) & 1;              \
            int t = j2 & 3, ks = j2 >> 3, ch = (j2 >> 2) & 1;                 \
            int slot = (((ks << 3) + mt) * 32 + (g << 2) + t) * 4 + (ch << 1) + rh; \
            Ah[slot] = *(uint32_t*)&hv;                                       \
        }                                                                     \
    } while (0)

    #define CPASYNC_B(BUF, S) do {                                            \
        _Pragma("unroll")                                                     \
        for (int c2 = 0; c2 < 2; c2++) {                                      \
            uint32_t dst = smem_u32(smem + OFF_B(BUF, c2)) + tid * 16;        \
            const uint4* src = (const uint4*)(g_Bh + ((S) * 2 + c2) * 2048) + tid; \
            asm volatile("cp.async.ca.shared.global [%0], [%1], 16;"          \
                         :: "r"(dst), "l"(src));                              \
            asm volatile("cp.async.ca.shared.global [%0], [%1], 16;"          \
                         :: "r"(dst + 4096), "l"(src + 256));                 \
        }                                                                     \
    } while (0)

    #define COMMIT  asm volatile("cp.async.commit_group;")
    #define WAIT0   asm volatile("cp.async.wait_group 0;" ::: "memory")

    #define COMPUTE(BUF) do {                                                 \
        _Pragma("unroll")                                                     \
        for (int c2 = 0; c2 < 2; c2++) {                                      \
            const uint4* Ah4 = (const uint4*)(smem + OFF_A(BUF, c2));         \
            const uint4* Bh4 = (const uint4*)(smem + OFF_B(BUF, c2));         \
            _Pragma("unroll")                                                 \
            for (int ks = 0; ks < 2; ks++) {                                  \
                uint4 ah0 = Ah4[((ks << 3) + wm * 2 + 0) * 32 + lane];        \
                uint4 ah1 = Ah4[((ks << 3) + wm * 2 + 1) * 32 + lane];        \
                _Pragma("unroll")                                             \
                for (int ntp = 0; ntp < 4; ntp++) {                           \
                    uint4 bb = Bh4[((ks << 3) + wn * 4 + ntp) * 32 + lane];   \
                    mma_f16(acc[0][2 * ntp],     ah0, bb.x, bb.y);            \
                    mma_f16(acc[1][2 * ntp],     ah1, bb.x, bb.y);            \
                    mma_f16(acc[0][2 * ntp + 1], ah0, bb.z, bb.w);            \
                    mma_f16(acc[1][2 * ntp + 1], ah1, bb.z, bb.w);            \
                }                                                             \
            }                                                                 \
        }                                                                     \
    } while (0)

    // ---- prologue: stage 0 into buffer 0 ----
    LOAD_X(0);
    CPASYNC_B(0, 0); COMMIT;
    STS_A(0);

    if (tid < D_) cb[tid] = bias[tid];
    if (tid < 128) {
        int p = p0 + tid;
        float med = 0.f;
        if (p < P_) {
            float v[KW];
            const float* tp = ts + b * L_ + p * STRIDE_;
            #pragma unroll
            for (int i = 0; i < KW; i++) v[i] = tp[i];
            #pragma unroll
            for (int pass = 0; pass < KW; pass++) {
                int st = pass & 1;
                #pragma unroll
                for (int i = 0; i < KW - 1; i++) {
                    if ((i & 1) == st) {
                        float lo = fminf(v[i], v[i + 1]);
                        float hi = fmaxf(v[i], v[i + 1]);
                        v[i] = lo; v[i + 1] = hi;
                    }
                }
            }
            med = v[(KW - 1) / 2];
        }
        smed[tid] = med;
    }
    WAIT0;
    __syncthreads();

    // ---- pipelined main loop: 8 stages, 1 sync each ----
    #pragma unroll 2
    for (int s = 0; s < NST; s++) {
        int buf = s & 1;
        if (s + 1 < NST) {
            LOAD_X(s + 1);                       // LDGs in flight over COMPUTE
            CPASYNC_B(buf ^ 1, s + 1); COMMIT;   // B for next stage in flight
        }
        COMPUTE(buf);
        if (s + 1 < NST) STS_A(buf ^ 1);         // LDG data has landed by now
        WAIT0;
        __syncthreads();
    }

    // ---- epilogue: bias + sinusoidal PE from median, write out ----
    {
        const int t = lane & 3, g = lane >> 2;
        float dt[8];
        #pragma unroll
        for (int nt = 0; nt < 8; nt++) {
            int i = wn * 32 + nt * 4 + t;                // d0/2
            dt[nt] = __expf((float)i * -0.14391156831f); // -ln(10000)*2/128
        }
        #pragma unroll
        for (int mt = 0; mt < 2; mt++) {
            int pl = wm * 32 + mt * 16 + g;
            #pragma unroll
            for (int half = 0; half < 2; half++) {
                int prow = pl + half * 8;
                int p = p0 + prow;
                if (p >= P_) continue;
                float med = smed[prow];
                float* orow = out + ((size_t)b * P_ + p) * D_;
                #pragma unroll
                for (int nt = 0; nt < 8; nt++) {
                    int d0 = wn * 64 + nt * 8 + 2 * t;
                    float sn, cs;
                    __sincosf(med * dt[nt], &sn, &cs);
                    float2 o;
                    o.x = acc[mt][nt][half * 2 + 0] + cb[d0] + sn;
                    o.y = acc[mt][nt][half * 2 + 1] + cb[d0 + 1] + cs;
                    *(float2*)(orow + d0) = o;
                }
            }
        }
    }
}

extern "C" void kernel_launch(void* const* d_in, const int* in_sizes, int n_in,
                              void* d_out, int out_size) {
    const float* x    = (const float*)d_in[0];
    const float* ts   = (const float*)d_in[1];
    const float* w    = (const float*)d_in[2];
    const float* bias = (const float*)d_in[3];
    float* out = (float*)d_out;

    prep_w_kernel<<<128, 256>>>(w);

    cudaFuncSetAttribute(encoder_hmma_kernel,
                         cudaFuncAttributeMaxDynamicSharedMemorySize, SM_TOTAL);
    dim3 grid(32, B_);
    encoder_hmma_kernel<<<grid, 256, SM_TOTAL>>>(x, ts, bias, out);
}